// round 2
// baseline (speedup 1.0000x reference)
#include <cuda_runtime.h>

// MeshConvPoint: B=8, C=64, V=25000, D=12, O=64
// out[b,o,v] = sum_c W[o,c,0]*x[b,c,v]
//            + (1/deg[b,v]) * sum_{d<deg} sum_c W[o,c,1]*x[b,c,nbr[b,v,d]]
//            + bias[o]
//
// Two-pass:
//  k1: z[b,v,o'] = sum_c x[b,c,v]*W[o,c,k], o' = k*64+o, stored v-major -> gathers become contiguous 256B rows
//  k2: per v gather 12 z1-rows (coalesced), mean, add self z0-row + bias, transpose via smem, coalesced store.

#define BB 8
#define CC 64
#define VV 25000
#define DD 12
#define OO 64

// scratch: [B][V][128] floats = 102.4 MB (device global; no runtime alloc)
__device__ float g_z[(size_t)BB * VV * 128];

using ull = unsigned long long;

__device__ __forceinline__ ull pack2(float lo, float hi) {
    ull r; asm("mov.b64 %0, {%1, %2};" : "=l"(r) : "f"(lo), "f"(hi)); return r;
}
__device__ __forceinline__ ull fma2(ull a, ull b, ull c) {
    ull d; asm("fma.rn.f32x2 %0, %1, %2, %3;" : "=l"(d) : "l"(a), "l"(b), "l"(c)); return d;
}
__device__ __forceinline__ float2 unpack2(ull a) {
    float2 f; asm("mov.b64 {%0, %1}, %2;" : "=f"(f.x), "=f"(f.y) : "l"(a)); return f;
}

// ---------------------------------------------------------------------------
// Kernel 1: per-batch GEMM  z[v, o'] = sum_c x[c,v] * Wsm[c, o']
// Tile: 64 v x 128 o' per block, 256 threads, thread = 4 o' x 8 v (v packed in pairs).
// ---------------------------------------------------------------------------
__global__ __launch_bounds__(256) void k1_gemm(const float* __restrict__ x,
                                               const float* __restrict__ W) {
    __shared__ float xs[64][64];    // [c][v_local]
    __shared__ float Ws[64][128];   // [c][o']  (o' = k*64 + o)

    const int b   = blockIdx.y;
    const int v0  = blockIdx.x * 64;
    const int tid = threadIdx.x;

    // W: [O=64][C=64][2] -> Ws[c][k*64+o]; read coalesced, write permuted
    for (int i = tid; i < 64 * 64 * 2; i += 256) {
        int o = i >> 7;
        int r = i & 127;
        int c = r >> 1;
        int k = r & 1;
        Ws[c][k * 64 + o] = W[i];
    }
    // x tile: [c][v], coalesced rows
    const float* xb = x + (size_t)b * CC * VV;
    for (int i = tid; i < 64 * 64; i += 256) {
        int c  = i >> 6;
        int v  = i & 63;
        int gv = v0 + v;
        xs[c][v] = (gv < VV) ? xb[(size_t)c * VV + gv] : 0.0f;
    }
    __syncthreads();

    const int og  = tid & 31;   // o-group: o0 = og*4 (lanes span o' 0..127 -> coalesced stores)
    const int vg  = tid >> 5;   // v-group: 8 v's per thread
    const int o0  = og * 4;
    const int vl0 = vg * 8;

    ull acc[4][4];  // [o][v-pair]
    #pragma unroll
    for (int i = 0; i < 4; i++)
        #pragma unroll
        for (int j = 0; j < 4; j++) acc[i][j] = 0ULL;

    #pragma unroll 8
    for (int c = 0; c < 64; c++) {
        float4 w4 = *reinterpret_cast<const float4*>(&Ws[c][o0]);
        ull wp[4];
        wp[0] = pack2(w4.x, w4.x);
        wp[1] = pack2(w4.y, w4.y);
        wp[2] = pack2(w4.z, w4.z);
        wp[3] = pack2(w4.w, w4.w);
        const ull* xr = reinterpret_cast<const ull*>(&xs[c][vl0]);
        ull xp[4];
        xp[0] = xr[0]; xp[1] = xr[1]; xp[2] = xr[2]; xp[3] = xr[3];
        #pragma unroll
        for (int i = 0; i < 4; i++)
            #pragma unroll
            for (int j = 0; j < 4; j++)
                acc[i][j] = fma2(xp[j], wp[i], acc[i][j]);
    }

    // store: per v, lanes cover o' 0..127 contiguously -> coalesced 512B
    float* zb = g_z + (size_t)b * VV * 128;
    #pragma unroll
    for (int j = 0; j < 4; j++) {
        float2 p0 = unpack2(acc[0][j]);
        float2 p1 = unpack2(acc[1][j]);
        float2 p2 = unpack2(acc[2][j]);
        float2 p3 = unpack2(acc[3][j]);
        int v = v0 + vl0 + 2 * j;
        if (v < VV)
            *reinterpret_cast<float4*>(&zb[(size_t)v * 128 + o0]) =
                make_float4(p0.x, p1.x, p2.x, p3.x);
        if (v + 1 < VV)
            *reinterpret_cast<float4*>(&zb[(size_t)(v + 1) * 128 + o0]) =
                make_float4(p0.y, p1.y, p2.y, p3.y);
    }
}

// ---------------------------------------------------------------------------
// Kernel 2: neighbor gather + epilogue. 32 v per block, 256 threads (8 warps).
// Warp w handles v_local = 4w..4w+3; lane covers o = lane and o = lane+32.
// ---------------------------------------------------------------------------
__global__ __launch_bounds__(256) void k2_gather(const int* __restrict__ nbr,
                                                 const int* __restrict__ deg,
                                                 const float* __restrict__ bias,
                                                 float* __restrict__ out) {
    __shared__ int   idx_s[32][DD];
    __shared__ int   deg_s[32];
    __shared__ float ob[64][33];   // [o][v], pad 33 -> conflict-free transpose

    const int b   = blockIdx.y;
    const int v0  = blockIdx.x * 32;
    const int tid = threadIdx.x;

    for (int i = tid; i < 32 * DD; i += 256) {
        int v  = i / DD;
        int d  = i % DD;
        int gv = v0 + v;
        idx_s[v][d] = (gv < VV) ? nbr[((size_t)b * VV + gv) * DD + d] : 0;
    }
    if (tid < 32) {
        int gv = v0 + tid;
        deg_s[tid] = (gv < VV) ? deg[(size_t)b * VV + gv] : 1;
    }
    __syncthreads();

    const int w    = tid >> 5;
    const int lane = tid & 31;
    const float* zb = g_z + (size_t)b * VV * 128;
    const float bias0 = __ldg(&bias[lane]);
    const float bias1 = __ldg(&bias[lane + 32]);

    float a0[4], a1[4];
    int   dg[4];
    #pragma unroll
    for (int j = 0; j < 4; j++) {
        a0[j] = 0.0f; a1[j] = 0.0f;
        dg[j] = deg_s[w * 4 + j];
    }

    #pragma unroll
    for (int d = 0; d < DD; d++) {
        #pragma unroll
        for (int j = 0; j < 4; j++) {
            if (d < dg[j]) {
                int nb = idx_s[w * 4 + j][d];
                const float* r = zb + (size_t)nb * 128 + 64;  // z1 half
                a0[j] += r[lane];
                a1[j] += r[lane + 32];
            }
        }
    }

    #pragma unroll
    for (int j = 0; j < 4; j++) {
        int vl = w * 4 + j;
        int gv = v0 + vl;
        if (gv < VV) {
            const float* s = zb + (size_t)gv * 128;           // z0 half
            float inv = 1.0f / (float)max(dg[j], 1);
            ob[lane][vl]      = s[lane]      + a0[j] * inv + bias0;
            ob[lane + 32][vl] = s[lane + 32] + a1[j] * inv + bias1;
        }
    }
    __syncthreads();

    // out: [B][O][V]; warp writes one o-row of 32 consecutive v -> coalesced
    for (int i = tid; i < 64 * 32; i += 256) {
        int o  = i >> 5;
        int v  = i & 31;
        int gv = v0 + v;
        if (gv < VV)
            out[((size_t)b * OO + o) * VV + gv] = ob[o][v];
    }
}

extern "C" void kernel_launch(void* const* d_in, const int* in_sizes, int n_in,
                              void* d_out, int out_size) {
    const float* x    = (const float*)d_in[0];
    const int*   nbr  = (const int*)d_in[1];
    const int*   deg  = (const int*)d_in[2];
    const float* W    = (const float*)d_in[3];
    const float* bias = (const float*)d_in[4];
    float*       out  = (float*)d_out;

    dim3 g1((VV + 63) / 64, BB);
    k1_gemm<<<g1, 256>>>(x, W);

    dim3 g2((VV + 31) / 32, BB);
    k2_gather<<<g2, 256>>>(nbr, deg, bias, out);
}

// round 3
// speedup vs baseline: 1.0599x; 1.0599x over previous
#include <cuda_runtime.h>
#include <cuda_fp16.h>

// MeshConvPoint: B=8, C=64, V=25000, D=12, O=64
// k1: z0[b,v,o] = sum_c x[b,c,v]*W[o,c,0]  (fp32, streamed once)
//     z1[b,v,o] = sum_c x[b,c,v]*W[o,c,1]  (fp16, gathered 12x -> 128B rows, L2-resident)
// k2: out[b,o,v] = z0 + (1/deg)*sum_{d<deg} z1[nbr] + bias

#define BB 8
#define CC 64
#define VV 25000
#define DD 12
#define OO 64

__device__ float  g_z0[(size_t)BB * VV * 64];   // 51.2 MB
__device__ __half g_z1[(size_t)BB * VV * 64];   // 25.6 MB (fits in L2)

using ull = unsigned long long;

__device__ __forceinline__ ull pack2(float lo, float hi) {
    ull r; asm("mov.b64 %0, {%1, %2};" : "=l"(r) : "f"(lo), "f"(hi)); return r;
}
__device__ __forceinline__ ull fma2(ull a, ull b, ull c) {
    ull d; asm("fma.rn.f32x2 %0, %1, %2, %3;" : "=l"(d) : "l"(a), "l"(b), "l"(c)); return d;
}
__device__ __forceinline__ float2 unpack2(ull a) {
    float2 f; asm("mov.b64 {%0, %1}, %2;" : "=f"(f.x), "=f"(f.y) : "l"(a)); return f;
}

// ---------------------------------------------------------------------------
// Kernel 1: per-batch GEMM. Tile 64 v x 128 o' (o'=k*64+o), 256 threads,
// thread = 4 o' x 8 v (v packed in f32x2 pairs). Unroll capped at 4 to avoid
// register spill (R1 post-mortem: unroll 8 suspected spilling -> 167us).
// ---------------------------------------------------------------------------
__global__ __launch_bounds__(256) void k1_gemm(const float* __restrict__ x,
                                               const float* __restrict__ W) {
    __shared__ float xs[64][64];    // [c][v_local]
    __shared__ float Ws[64][128];   // [c][o']

    const int b   = blockIdx.y;
    const int v0  = blockIdx.x * 64;
    const int tid = threadIdx.x;

    // W: [O=64][C=64][2] -> Ws[c][k*64+o]
    for (int i = tid; i < 64 * 64 * 2; i += 256) {
        int o = i >> 7;
        int r = i & 127;
        int c = r >> 1;
        int k = r & 1;
        Ws[c][k * 64 + o] = W[i];
    }
    const float* xb = x + (size_t)b * CC * VV;
    for (int i = tid; i < 64 * 64; i += 256) {
        int c  = i >> 6;
        int v  = i & 63;
        int gv = v0 + v;
        xs[c][v] = (gv < VV) ? xb[(size_t)c * VV + gv] : 0.0f;
    }
    __syncthreads();

    const int og  = tid & 31;   // lanes span o' 0..127 -> coalesced stores
    const int vg  = tid >> 5;
    const int o0  = og * 4;
    const int vl0 = vg * 8;

    ull acc[4][4];  // [o][v-pair]
    #pragma unroll
    for (int i = 0; i < 4; i++)
        #pragma unroll
        for (int j = 0; j < 4; j++) acc[i][j] = 0ULL;

    #pragma unroll 4
    for (int c = 0; c < 64; c++) {
        float4 w4 = *reinterpret_cast<const float4*>(&Ws[c][o0]);       // LDS.128
        ull wp0 = pack2(w4.x, w4.x);
        ull wp1 = pack2(w4.y, w4.y);
        ull wp2 = pack2(w4.z, w4.z);
        ull wp3 = pack2(w4.w, w4.w);
        ulonglong2 xa = *reinterpret_cast<const ulonglong2*>(&xs[c][vl0]);     // LDS.128
        ulonglong2 xc = *reinterpret_cast<const ulonglong2*>(&xs[c][vl0 + 4]); // LDS.128
        ull xp[4] = {xa.x, xa.y, xc.x, xc.y};
        #pragma unroll
        for (int j = 0; j < 4; j++) {
            acc[0][j] = fma2(xp[j], wp0, acc[0][j]);
            acc[1][j] = fma2(xp[j], wp1, acc[1][j]);
            acc[2][j] = fma2(xp[j], wp2, acc[2][j]);
            acc[3][j] = fma2(xp[j], wp3, acc[3][j]);
        }
    }

    // store: lanes 0..15 own z0 (fp32), lanes 16..31 own z1 (fp16)
    float*  z0b = g_z0 + (size_t)b * VV * 64;
    __half* z1b = g_z1 + (size_t)b * VV * 64;
    const bool is1 = (o0 >= 64);
    const int  oo  = is1 ? (o0 - 64) : o0;

    #pragma unroll
    for (int j = 0; j < 4; j++) {
        float2 p0 = unpack2(acc[0][j]);
        float2 p1 = unpack2(acc[1][j]);
        float2 p2 = unpack2(acc[2][j]);
        float2 p3 = unpack2(acc[3][j]);
        int v = v0 + vl0 + 2 * j;
        #pragma unroll
        for (int h = 0; h < 2; h++) {
            int vv = v + h;
            if (vv >= VV) continue;
            float e0 = h ? p0.y : p0.x;
            float e1 = h ? p1.y : p1.x;
            float e2 = h ? p2.y : p2.x;
            float e3 = h ? p3.y : p3.x;
            if (!is1) {
                *reinterpret_cast<float4*>(&z0b[(size_t)vv * 64 + oo]) =
                    make_float4(e0, e1, e2, e3);
            } else {
                __half2 h01 = __floats2half2_rn(e0, e1);
                __half2 h23 = __floats2half2_rn(e2, e3);
                uint2 u;
                u.x = *reinterpret_cast<unsigned*>(&h01);
                u.y = *reinterpret_cast<unsigned*>(&h23);
                *reinterpret_cast<uint2*>(&z1b[(size_t)vv * 64 + oo]) = u;
            }
        }
    }
}

// ---------------------------------------------------------------------------
// Kernel 2: gather + epilogue. 32 v per block, 256 threads (8 warps).
// Warp w: v_local = 4w..4w+3; lane owns o-pair (2*lane, 2*lane+1).
// Each (v,d) gather = one 128B coalesced line of fp16 z1.
// ---------------------------------------------------------------------------
__global__ __launch_bounds__(256) void k2_gather(const int* __restrict__ nbr,
                                                 const int* __restrict__ deg,
                                                 const float* __restrict__ bias,
                                                 float* __restrict__ out) {
    __shared__ int   idx_s[32][DD];
    __shared__ int   deg_s[32];
    __shared__ float ob[64][33];

    const int b   = blockIdx.y;
    const int v0  = blockIdx.x * 32;
    const int tid = threadIdx.x;

    for (int i = tid; i < 32 * DD; i += 256) {
        int v  = i / DD;
        int d  = i % DD;
        int gv = v0 + v;
        idx_s[v][d] = (gv < VV) ? nbr[((size_t)b * VV + gv) * DD + d] : 0;
    }
    if (tid < 32) {
        int gv = v0 + tid;
        deg_s[tid] = (gv < VV) ? deg[(size_t)b * VV + gv] : 1;
    }
    __syncthreads();

    const int w    = tid >> 5;
    const int lane = tid & 31;
    const float*   z0b = g_z0 + (size_t)b * VV * 64;
    const __half2* z1b = reinterpret_cast<const __half2*>(g_z1 + (size_t)b * VV * 64);
    const float2 bia = *reinterpret_cast<const float2*>(&bias[2 * lane]);

    float2 a[4];
    int    dg[4];
    #pragma unroll
    for (int j = 0; j < 4; j++) {
        a[j] = make_float2(0.0f, 0.0f);
        dg[j] = deg_s[w * 4 + j];
    }

    #pragma unroll
    for (int d = 0; d < DD; d++) {
        #pragma unroll
        for (int j = 0; j < 4; j++) {
            if (d < dg[j]) {
                int nb = idx_s[w * 4 + j][d];
                float2 f = __half22float2(z1b[(size_t)nb * 32 + lane]);  // 128B/warp
                a[j].x += f.x;
                a[j].y += f.y;
            }
        }
    }

    #pragma unroll
    for (int j = 0; j < 4; j++) {
        int vl = w * 4 + j;
        int gv = v0 + vl;
        if (gv < VV) {
            float2 s  = *reinterpret_cast<const float2*>(&z0b[(size_t)gv * 64 + 2 * lane]);
            float inv = 1.0f / (float)max(dg[j], 1);
            ob[2 * lane][vl]     = s.x + a[j].x * inv + bia.x;
            ob[2 * lane + 1][vl] = s.y + a[j].y * inv + bia.y;
        }
    }
    __syncthreads();

    for (int i = tid; i < 64 * 32; i += 256) {
        int o  = i >> 5;
        int v  = i & 31;
        int gv = v0 + v;
        if (gv < VV)
            out[((size_t)b * OO + o) * VV + gv] = ob[o][v];
    }
}

extern "C" void kernel_launch(void* const* d_in, const int* in_sizes, int n_in,
                              void* d_out, int out_size) {
    const float* x    = (const float*)d_in[0];
    const int*   nbr  = (const int*)d_in[1];
    const int*   deg  = (const int*)d_in[2];
    const float* W    = (const float*)d_in[3];
    const float* bias = (const float*)d_in[4];
    float*       out  = (float*)d_out;

    dim3 g1((VV + 63) / 64, BB);
    k1_gemm<<<g1, 256>>>(x, W);

    dim3 g2((VV + 31) / 32, BB);
    k2_gather<<<g2, 256>>>(nbr, deg, bias, out);
}

// round 6
// speedup vs baseline: 1.1114x; 1.0485x over previous
#include <cuda_runtime.h>
#include <cuda_fp16.h>
#include <cstdint>

// MeshConvPoint: B=8, C=64, V=25000, D=12, O=64
// k1 (HMMA mma.sync): Z[b,v,o'] = sum_c x[b,c,v] * W[o,c,k], o'=k*64+o
//   fp16 hi/lo split, 3 passes (hh, h*lo, lo*h), fp32 accumulate -> ~eps^2 error.
//   z0 (k=0) stored fp32; z1 (k=1) stored fp16 (128B rows, L2-resident).
// k2: out = z0 + (1/deg)*sum z1[nbr] + bias. Branch-free gathers via a
//   permanently-zero padding row, 32-bit offset math.

#define BB 8
#define CC 64
#define VV 25000
#define DD 12
#define OO 64

__device__ float  g_z0[(size_t)BB * VV * 64];          // 51.2 MB
__device__ __half g_z1[((size_t)BB * VV + 1) * 64];    // 25.6 MB + zero row (bss-zeroed, never written)

__device__ __forceinline__ uint32_t smem_u32(const void* p) {
    uint32_t a;
    asm("{ .reg .u64 t; cvta.to.shared.u64 t, %1; cvt.u32.u64 %0, t; }" : "=r"(a) : "l"(p));
    return a;
}
__device__ __forceinline__ void ldsm_x4(uint32_t& r0, uint32_t& r1, uint32_t& r2, uint32_t& r3,
                                        uint32_t addr) {
    asm volatile("ldmatrix.sync.aligned.m8n8.x4.shared.b16 {%0,%1,%2,%3}, [%4];"
                 : "=r"(r0), "=r"(r1), "=r"(r2), "=r"(r3) : "r"(addr));
}
__device__ __forceinline__ void ldsm_x2(uint32_t& r0, uint32_t& r1, uint32_t addr) {
    asm volatile("ldmatrix.sync.aligned.m8n8.x2.shared.b16 {%0,%1}, [%2];"
                 : "=r"(r0), "=r"(r1) : "r"(addr));
}
__device__ __forceinline__ void mma16816(float* c, const uint32_t* a, const uint32_t* bfr) {
    asm volatile(
        "mma.sync.aligned.m16n8k16.row.col.f32.f16.f16.f32 "
        "{%0,%1,%2,%3}, {%4,%5,%6,%7}, {%8,%9}, {%0,%1,%2,%3};"
        : "+f"(c[0]), "+f"(c[1]), "+f"(c[2]), "+f"(c[3])
        : "r"(a[0]), "r"(a[1]), "r"(a[2]), "r"(a[3]), "r"(bfr[0]), "r"(bfr[1]));
}

// dynamic smem layout (bytes). Row stride 144B (72 halves) -> conflict-free ldmatrix.
#define LDB     144
#define SM_A_HI 0
#define SM_A_LO (SM_A_HI + 64 * LDB)       //  9216
#define SM_B_HI (SM_A_LO + 64 * LDB)       // 18432
#define SM_B_LO (SM_B_HI + 128 * LDB)      // 36864
#define SM_ST   (SM_B_LO + 128 * LDB)      // 55296
#define SM_TOTAL (SM_ST + 64 * 65 * 4)     // 71936

// ---------------------------------------------------------------------------
// Kernel 1: one 64v x 128o' tile per block, 128 threads (4 warps).
// Warp w owns o' columns [32w, 32w+32). Warps 0-1 -> z0 (fp32), 2-3 -> z1 (fp16).
// ---------------------------------------------------------------------------
__global__ __launch_bounds__(128) void k1_gemm(const float* __restrict__ x,
                                               const float* __restrict__ W) {
    extern __shared__ char smem[];
    const uint32_t sb = smem_u32(smem);
    const int tid = threadIdx.x, wid = tid >> 5, lane = tid & 31;
    const int b = blockIdx.y, v0 = blockIdx.x * 64;

    // ---- W prep: thread t owns B-row o' = t (kk = t>>6, o = t&63), hi/lo split ----
    {
        const int kk = tid >> 6, o = tid & 63;
        #pragma unroll
        for (int g = 0; g < 8; g++) {
            __half hi8[8], lo8[8];
            #pragma unroll
            for (int cc = 0; cc < 8; cc++) {
                float wv = W[((size_t)o * 64 + g * 8 + cc) * 2 + kk];
                __half h = __float2half_rn(wv);
                hi8[cc] = h;
                lo8[cc] = __float2half_rn(wv - __half2float(h));
            }
            uint32_t off = (uint32_t)tid * LDB + g * 16;
            *reinterpret_cast<uint4*>(smem + SM_B_HI + off) = *reinterpret_cast<uint4*>(hi8);
            *reinterpret_cast<uint4*>(smem + SM_B_LO + off) = *reinterpret_cast<uint4*>(lo8);
        }
    }

    // ---- x tile: load [c][v] coalesced, transpose+split to A_HI/A_LO [v][c] ----
    float* stage = reinterpret_cast<float*>(smem + SM_ST);   // [64][65]
    const float* xb = x + (size_t)b * CC * VV;
    for (int i = tid; i < 64 * 64; i += 128) {
        int c = i >> 6, v = i & 63;
        int gv = v0 + v;
        stage[c * 65 + v] = (gv < VV) ? xb[(size_t)c * VV + gv] : 0.0f;
    }
    __syncthreads();
    {
        const int v = tid & 63, chalf = tid >> 6;
        #pragma unroll
        for (int g = 0; g < 4; g++) {
            const int c0 = chalf * 32 + g * 8;
            __half hi8[8], lo8[8];
            #pragma unroll
            for (int cc = 0; cc < 8; cc++) {
                float f = stage[(c0 + cc) * 65 + v];
                __half h = __float2half_rn(f);
                hi8[cc] = h;
                lo8[cc] = __float2half_rn(f - __half2float(h));
            }
            uint32_t off = (uint32_t)v * LDB + c0 * 2;
            *reinterpret_cast<uint4*>(smem + SM_A_HI + off) = *reinterpret_cast<uint4*>(hi8);
            *reinterpret_cast<uint4*>(smem + SM_A_LO + off) = *reinterpret_cast<uint4*>(lo8);
        }
    }
    __syncthreads();

    // ---- MMA: 3 passes (A_hi*B_hi, A_hi*B_lo, A_lo*B_hi), K=64 in 4 steps ----
    float acc[4][4][4];   // [mt][nt][reg]
    #pragma unroll
    for (int mt = 0; mt < 4; mt++)
        #pragma unroll
        for (int nt = 0; nt < 4; nt++)
            #pragma unroll
            for (int q = 0; q < 4; q++) acc[mt][nt][q] = 0.0f;

    const uint32_t a_row  = (lane & 15), a_half = (lane >> 4);
    const uint32_t b_row  = (lane & 7),  b_half = (lane >> 3) & 1;

    #pragma unroll
    for (int pass = 0; pass < 3; pass++) {
        const uint32_t abase = sb + ((pass == 2) ? SM_A_LO : SM_A_HI);
        const uint32_t bbase = sb + ((pass == 1) ? SM_B_LO : SM_B_HI);
        #pragma unroll
        for (int ks = 0; ks < 4; ks++) {
            uint32_t af[4][4];
            #pragma unroll
            for (int mt = 0; mt < 4; mt++) {
                uint32_t addr = abase + (mt * 16 + a_row) * LDB + ks * 32 + a_half * 16;
                ldsm_x4(af[mt][0], af[mt][1], af[mt][2], af[mt][3], addr);
            }
            uint32_t bf[4][2];
            #pragma unroll
            for (int nt = 0; nt < 4; nt++) {
                uint32_t addr = bbase + (wid * 32 + nt * 8 + b_row) * LDB + ks * 32 + b_half * 16;
                ldsm_x2(bf[nt][0], bf[nt][1], addr);
            }
            #pragma unroll
            for (int mt = 0; mt < 4; mt++)
                #pragma unroll
                for (int nt = 0; nt < 4; nt++)
                    mma16816(acc[mt][nt], af[mt], bf[nt]);
        }
    }

    // ---- epilogue: direct stores. lane l: rows l/4 (+8), cols (l%4)*2 (+1) ----
    const int r  = lane >> 2, cp = (lane & 3) * 2;
    float*  z0p = g_z0 + (size_t)b * VV * 64;
    __half* z1p = g_z1 + (size_t)b * VV * 64;

    if (wid < 2) {                       // o' in [0,64): z0 fp32
        #pragma unroll
        for (int mt = 0; mt < 4; mt++) {
            int v1 = v0 + mt * 16 + r;
            #pragma unroll
            for (int nt = 0; nt < 4; nt++) {
                int op = wid * 32 + nt * 8 + cp;
                if (v1 < VV)
                    *reinterpret_cast<float2*>(z0p + (size_t)v1 * 64 + op) =
                        make_float2(acc[mt][nt][0], acc[mt][nt][1]);
                if (v1 + 8 < VV)
                    *reinterpret_cast<float2*>(z0p + (size_t)(v1 + 8) * 64 + op) =
                        make_float2(acc[mt][nt][2], acc[mt][nt][3]);
            }
        }
    } else {                             // o' in [64,128): z1 fp16
        #pragma unroll
        for (int mt = 0; mt < 4; mt++) {
            int v1 = v0 + mt * 16 + r;
            #pragma unroll
            for (int nt = 0; nt < 4; nt++) {
                int oo = (wid - 2) * 32 + nt * 8 + cp;
                if (v1 < VV) {
                    __half2 h = __floats2half2_rn(acc[mt][nt][0], acc[mt][nt][1]);
                    *reinterpret_cast<__half2*>(z1p + (size_t)v1 * 64 + oo) = h;
                }
                if (v1 + 8 < VV) {
                    __half2 h = __floats2half2_rn(acc[mt][nt][2], acc[mt][nt][3]);
                    *reinterpret_cast<__half2*>(z1p + (size_t)(v1 + 8) * 64 + oo) = h;
                }
            }
        }
    }
}

// ---------------------------------------------------------------------------
// Kernel 2: 32 v per block, 256 threads. Branch-free gathers (zero-row pad),
// 32-bit offset math. Warp w: v_local 4w..4w+3, lane owns o-pair via half2.
// ---------------------------------------------------------------------------
__global__ __launch_bounds__(256) void k2_gather(const int* __restrict__ nbr,
                                                 const int* __restrict__ deg,
                                                 const float* __restrict__ bias,
                                                 float* __restrict__ out) {
    __shared__ int   rows[32][DD];   // absolute safe z1 row indices
    __shared__ int   deg_s[32];
    __shared__ float ob[64][33];

    const int b = blockIdx.y, v0 = blockIdx.x * 32, tid = threadIdx.x;

    if (tid < 32) {
        int gv = v0 + tid;
        deg_s[tid] = (gv < VV) ? deg[(size_t)b * VV + gv] : 0;
    }
    __syncthreads();
    for (int i = tid; i < 32 * DD; i += 256) {
        int v = i / DD, d = i % DD;
        int gv = v0 + v;
        int rr = BB * VV;                                 // zero row
        if (gv < VV && d < deg_s[v])
            rr = b * VV + nbr[((size_t)b * VV + gv) * DD + d];
        rows[v][d] = rr;
    }
    __syncthreads();

    const int w = tid >> 5, lane = tid & 31;
    const __half2* z1p = reinterpret_cast<const __half2*>(g_z1);
    const float2 bia = *reinterpret_cast<const float2*>(bias + 2 * lane);

    #pragma unroll
    for (int j = 0; j < 4; j++) {
        const int vl = w * 4 + j;
        float2 a = make_float2(0.0f, 0.0f);
        #pragma unroll
        for (int d = 0; d < DD; d++) {
            int off = rows[vl][d] * 32 + lane;            // 32-bit IMAD
            float2 f = __half22float2(z1p[off]);          // 128B coalesced/warp
            a.x += f.x;
            a.y += f.y;
        }
        int gv = v0 + vl;
        if (gv < VV) {
            float2 s = *reinterpret_cast<const float2*>(g_z0 + ((size_t)b * VV + gv) * 64 + 2 * lane);
            float inv = 1.0f / (float)max(deg_s[vl], 1);
            ob[2 * lane][vl]     = s.x + a.x * inv + bia.x;
            ob[2 * lane + 1][vl] = s.y + a.y * inv + bia.y;
        }
    }
    __syncthreads();

    for (int i = tid; i < 64 * 32; i += 256) {
        int o = i >> 5, v = i & 31;
        int gv = v0 + v;
        if (gv < VV)
            out[((size_t)b * OO + o) * VV + gv] = ob[o][v];
    }
}

extern "C" void kernel_launch(void* const* d_in, const int* in_sizes, int n_in,
                              void* d_out, int out_size) {
    const float* x    = (const float*)d_in[0];
    const int*   nbr  = (const int*)d_in[1];
    const int*   deg  = (const int*)d_in[2];
    const float* W    = (const float*)d_in[3];
    const float* bias = (const float*)d_in[4];
    float*       out  = (float*)d_out;

    cudaFuncSetAttribute(k1_gemm, cudaFuncAttributeMaxDynamicSharedMemorySize, SM_TOTAL);

    dim3 g1((VV + 63) / 64, BB);
    k1_gemm<<<g1, 128, SM_TOTAL>>>(x, W);

    dim3 g2((VV + 31) / 32, BB);
    k2_gather<<<g2, 256>>>(nbr, deg, bias, out);
}

// round 7
// speedup vs baseline: 1.7778x; 1.5996x over previous
#include <cuda_runtime.h>
#include <cuda_fp16.h>
#include <cstdint>

// MeshConvPoint: B=8, C=64, V=25000, D=12, O=64
// k1 (HMMA, pipelined): Z[b,v,o'] = sum_c x[b,c,v] * W[o,c,k], o'=k*64+o
//   fp16 hi/lo split, 3 passes (hh, h*lo, lo*h), fp32 accumulate.
//   x stored [c][v] in smem (fp16), A fragments via ldmatrix.trans (no stage xpose).
//   W split once per block, amortized over a multi-tile loop; A double-buffered,
//   next tile's LDGs issued before current MMA.
//   z0 (k=0) fp32; z1 (k=1) fp16 (128B rows, L2-resident).
// k2: out = z0 + (1/deg)*sum z1[nbr] + bias. Branch-free gathers (zero-row pad),
//   half2 accumulation (no per-gather cvt), pre-scaled 32-bit offsets.

#define BB 8
#define CC 64
#define VV 25000
#define DD 12
#define OO 64
#define NT 391            // ceil(VV/64) v-tiles
#define GX 56             // k1 grid.x (56*8=448 blocks ~ 3/SM)

__device__ float  g_z0[(size_t)BB * VV * 64];          // 51.2 MB
__device__ __half g_z1[((size_t)BB * VV + 1) * 64];    // 25.6 MB + zero row (bss-zeroed, never written)

__device__ __forceinline__ uint32_t smem_u32(const void* p) {
    uint32_t a;
    asm("{ .reg .u64 t; cvta.to.shared.u64 t, %1; cvt.u32.u64 %0, t; }" : "=r"(a) : "l"(p));
    return a;
}
__device__ __forceinline__ void ldsm_x4_t(uint32_t& r0, uint32_t& r1, uint32_t& r2, uint32_t& r3,
                                          uint32_t addr) {
    asm volatile("ldmatrix.sync.aligned.m8n8.x4.trans.shared.b16 {%0,%1,%2,%3}, [%4];"
                 : "=r"(r0), "=r"(r1), "=r"(r2), "=r"(r3) : "r"(addr));
}
__device__ __forceinline__ void ldsm_x2(uint32_t& r0, uint32_t& r1, uint32_t addr) {
    asm volatile("ldmatrix.sync.aligned.m8n8.x2.shared.b16 {%0,%1}, [%2];"
                 : "=r"(r0), "=r"(r1) : "r"(addr));
}
__device__ __forceinline__ void mma16816(float* c, const uint32_t* a, const uint32_t* bfr) {
    asm volatile(
        "mma.sync.aligned.m16n8k16.row.col.f32.f16.f16.f32 "
        "{%0,%1,%2,%3}, {%4,%5,%6,%7}, {%8,%9}, {%0,%1,%2,%3};"
        : "+f"(c[0]), "+f"(c[1]), "+f"(c[2]), "+f"(c[3])
        : "r"(a[0]), "r"(a[1]), "r"(a[2]), "r"(a[3]), "r"(bfr[0]), "r"(bfr[1]));
}
__device__ __forceinline__ uint32_t packh2(__half a, __half b) {
    __half2 h = __halves2half2(a, b);
    return *reinterpret_cast<uint32_t*>(&h);
}

// smem layout (bytes), row stride 144 -> conflict-free ldmatrix
#define LDB    144
#define SM_BHI 0
#define SM_BLO (SM_BHI + 128 * LDB)       // 18432
#define SM_A0H (SM_BLO + 128 * LDB)       // 36864
#define SM_A0L (SM_A0H + 64 * LDB)        // 46080
#define SM_A1H (SM_A0L + 64 * LDB)        // 55296
#define SM_A1L (SM_A1H + 64 * LDB)        // 64512
#define SM_TOTAL (SM_A1L + 64 * LDB)      // 73728

// ---------------------------------------------------------------------------
// Kernel 1: 256 threads (8 warps, warp-grid 2m x 4n). Tile = 64v x 128o'.
// Block loops over v-tiles t = bx, bx+GX, ... with double-buffered A.
// ---------------------------------------------------------------------------
__global__ __launch_bounds__(256, 3) void k1_gemm(const float* __restrict__ x,
                                                  const float* __restrict__ W) {
    extern __shared__ char smem[];
    const uint32_t sb = smem_u32(smem);
    const int tid = threadIdx.x, wid = tid >> 5, lane = tid & 31;
    const int b = blockIdx.y, bx = blockIdx.x;
    const int mh = wid >> 2, nq = wid & 3;

    // ---- W prep (once per block): 1024 items = 128 o'-rows x 8 c-groups ----
    for (int i = tid; i < 1024; i += 256) {
        int op = i >> 3, g = i & 7;       // B-row o' = kk*64+o, c-group
        int o = op & 63, kk = op >> 6;
        __half hi8[8], lo8[8];
        #pragma unroll
        for (int cc = 0; cc < 8; cc++) {
            float wv = W[((size_t)o * 64 + g * 8 + cc) * 2 + kk];
            __half h = __float2half_rn(wv);
            hi8[cc] = h;
            lo8[cc] = __float2half_rn(wv - __half2float(h));
        }
        uint32_t off = (uint32_t)op * LDB + g * 16;
        *reinterpret_cast<uint4*>(smem + SM_BHI + off) = *reinterpret_cast<uint4*>(hi8);
        *reinterpret_cast<uint4*>(smem + SM_BLO + off) = *reinterpret_cast<uint4*>(lo8);
    }

    const float* xb = x + (size_t)b * CC * VV;
    const int c  = tid >> 2;              // x row this thread loads/converts
    const int vs = (tid & 3) * 16;        // 16 v's = 4 float4

    float4 f[4];
    // prologue: load tile bx
    {
        const int v0 = bx * 64;
        #pragma unroll
        for (int j = 0; j < 4; j++) {
            int vbse = v0 + vs + 4 * j;
            f[j] = (vbse + 3 < VV) ? *reinterpret_cast<const float4*>(xb + (size_t)c * VV + vbse)
                                   : make_float4(0.f, 0.f, 0.f, 0.f);
        }
    }
    // fill A[0]
    {
        uint32_t offH = SM_A0H + (uint32_t)c * LDB + vs * 2;
        uint32_t offL = SM_A0L + (uint32_t)c * LDB + vs * 2;
        #pragma unroll
        for (int j = 0; j < 4; j++) {
            __half h0 = __float2half_rn(f[j].x), h1 = __float2half_rn(f[j].y);
            __half h2 = __float2half_rn(f[j].z), h3 = __float2half_rn(f[j].w);
            uint2 uh = make_uint2(packh2(h0, h1), packh2(h2, h3));
            uint2 ul = make_uint2(packh2(__float2half_rn(f[j].x - __half2float(h0)),
                                         __float2half_rn(f[j].y - __half2float(h1))),
                                  packh2(__float2half_rn(f[j].z - __half2float(h2)),
                                         __float2half_rn(f[j].w - __half2float(h3))));
            *reinterpret_cast<uint2*>(smem + offH + j * 8) = uh;
            *reinterpret_cast<uint2*>(smem + offL + j * 8) = ul;
        }
    }

    const int r  = lane >> 2, cp = (lane & 3) * 2;
    float*  z0p = g_z0 + (size_t)b * VV * 64;
    __half* z1p = g_z1 + (size_t)b * VV * 64;

    int buf = 0;
    for (int t = bx; t < NT; t += GX) {
        __syncthreads();                  // A[buf] (and W on iter 0) visible
        const int tn = t + GX;

        // prefetch next tile's x into regs (in flight during MMA)
        if (tn < NT) {
            const int v0n = tn * 64;
            #pragma unroll
            for (int j = 0; j < 4; j++) {
                int vbse = v0n + vs + 4 * j;
                f[j] = (vbse + 3 < VV) ? *reinterpret_cast<const float4*>(xb + (size_t)c * VV + vbse)
                                       : make_float4(0.f, 0.f, 0.f, 0.f);
            }
        }

        // ---- MMA on A[buf]: 3 passes, K=64 in 4 steps ----
        float acc[2][4][4];
        #pragma unroll
        for (int mt = 0; mt < 2; mt++)
            #pragma unroll
            for (int nt = 0; nt < 4; nt++)
                #pragma unroll
                for (int q = 0; q < 4; q++) acc[mt][nt][q] = 0.0f;

        const uint32_t AH = sb + (buf ? SM_A1H : SM_A0H);
        const uint32_t AL = sb + (buf ? SM_A1L : SM_A0L);
        #pragma unroll
        for (int pass = 0; pass < 3; pass++) {
            const uint32_t Ab = (pass == 2) ? AL : AH;
            const uint32_t Bb = sb + ((pass == 1) ? SM_BLO : SM_BHI);
            #pragma unroll
            for (int ks = 0; ks < 4; ks++) {
                uint32_t af[2][4];
                #pragma unroll
                for (int mt = 0; mt < 2; mt++) {
                    uint32_t r0, r1, r2, r3;
                    uint32_t addr = Ab + (ks * 16 + (lane & 15)) * LDB
                                  + (mh * 32 + mt * 16) * 2 + (lane >> 4) * 16;
                    ldsm_x4_t(r0, r1, r2, r3, addr);
                    af[mt][0] = r0; af[mt][1] = r2; af[mt][2] = r1; af[mt][3] = r3;
                }
                uint32_t bf[4][2];
                #pragma unroll
                for (int nt = 0; nt < 4; nt++) {
                    uint32_t addr = Bb + (nq * 32 + nt * 8 + (lane & 7)) * LDB
                                  + ks * 32 + ((lane >> 3) & 1) * 16;
                    ldsm_x2(bf[nt][0], bf[nt][1], addr);
                }
                #pragma unroll
                for (int mt = 0; mt < 2; mt++)
                    #pragma unroll
                    for (int nt = 0; nt < 4; nt++)
                        mma16816(acc[mt][nt], af[mt], bf[nt]);
            }
        }

        // fill other buffer with prefetched tile (no sync needed: last reads of
        // A[buf^1] happened before this iteration's __syncthreads)
        if (tn < NT) {
            uint32_t offH = (buf ? SM_A0H : SM_A1H) + (uint32_t)c * LDB + vs * 2;
            uint32_t offL = (buf ? SM_A0L : SM_A1L) + (uint32_t)c * LDB + vs * 2;
            #pragma unroll
            for (int j = 0; j < 4; j++) {
                __half h0 = __float2half_rn(f[j].x), h1 = __float2half_rn(f[j].y);
                __half h2 = __float2half_rn(f[j].z), h3 = __float2half_rn(f[j].w);
                uint2 uh = make_uint2(packh2(h0, h1), packh2(h2, h3));
                uint2 ul = make_uint2(packh2(__float2half_rn(f[j].x - __half2float(h0)),
                                             __float2half_rn(f[j].y - __half2float(h1))),
                                      packh2(__float2half_rn(f[j].z - __half2float(h2)),
                                             __float2half_rn(f[j].w - __half2float(h3))));
                *reinterpret_cast<uint2*>(smem + offH + j * 8) = uh;
                *reinterpret_cast<uint2*>(smem + offL + j * 8) = ul;
            }
        }

        // ---- epilogue: nq 0-1 -> z0 fp32, nq 2-3 -> z1 fp16 ----
        const int v0 = t * 64;
        if (nq < 2) {
            #pragma unroll
            for (int mt = 0; mt < 2; mt++) {
                int v1 = v0 + mh * 32 + mt * 16 + r;
                #pragma unroll
                for (int nt = 0; nt < 4; nt++) {
                    int op = nq * 32 + nt * 8 + cp;
                    if (v1 < VV)
                        *reinterpret_cast<float2*>(z0p + (size_t)v1 * 64 + op) =
                            make_float2(acc[mt][nt][0], acc[mt][nt][1]);
                    if (v1 + 8 < VV)
                        *reinterpret_cast<float2*>(z0p + (size_t)(v1 + 8) * 64 + op) =
                            make_float2(acc[mt][nt][2], acc[mt][nt][3]);
                }
            }
        } else {
            #pragma unroll
            for (int mt = 0; mt < 2; mt++) {
                int v1 = v0 + mh * 32 + mt * 16 + r;
                #pragma unroll
                for (int nt = 0; nt < 4; nt++) {
                    int oo = (nq - 2) * 32 + nt * 8 + cp;
                    if (v1 < VV) {
                        __half2 h = __floats2half2_rn(acc[mt][nt][0], acc[mt][nt][1]);
                        *reinterpret_cast<__half2*>(z1p + (size_t)v1 * 64 + oo) = h;
                    }
                    if (v1 + 8 < VV) {
                        __half2 h = __floats2half2_rn(acc[mt][nt][2], acc[mt][nt][3]);
                        *reinterpret_cast<__half2*>(z1p + (size_t)(v1 + 8) * 64 + oo) = h;
                    }
                }
            }
        }
        buf ^= 1;
    }
}

// ---------------------------------------------------------------------------
// Kernel 2: 32 v per block, 256 threads. Branch-free gathers (zero-row pad),
// pre-scaled 32-bit offsets, half2 accumulation (no per-gather cvt).
// ---------------------------------------------------------------------------
__global__ __launch_bounds__(256) void k2_gather(const int* __restrict__ nbr,
                                                 const int* __restrict__ deg,
                                                 const float* __restrict__ bias,
                                                 float* __restrict__ out) {
    __shared__ int   rows32[32][DD];   // safe z1 row index * 32
    __shared__ int   deg_s[32];
    __shared__ float ob[64][33];

    const int b = blockIdx.y, v0 = blockIdx.x * 32, tid = threadIdx.x;

    if (tid < 32) {
        int gv = v0 + tid;
        deg_s[tid] = (gv < VV) ? deg[(size_t)b * VV + gv] : 0;
    }
    __syncthreads();
    for (int i = tid; i < 32 * DD; i += 256) {
        int v = i / DD, d = i % DD;
        int gv = v0 + v;
        int rr = BB * VV;                                 // zero row
        if (gv < VV && d < deg_s[v])
            rr = b * VV + nbr[((size_t)b * VV + gv) * DD + d];
        rows32[v][d] = rr * 32;
    }
    __syncthreads();

    const int w = tid >> 5, lane = tid & 31;
    const __half2* z1p = reinterpret_cast<const __half2*>(g_z1);
    const float2 bia = *reinterpret_cast<const float2*>(bias + 2 * lane);

    #pragma unroll
    for (int j = 0; j < 4; j++) {
        const int vl = w * 4 + j;
        __half2 a = __halves2half2(__ushort_as_half(0), __ushort_as_half(0));
        #pragma unroll
        for (int d = 0; d < DD; d++) {
            int off = rows32[vl][d] + lane;               // IADD
            a = __hadd2(a, z1p[off]);                     // 128B coalesced/warp
        }
        int gv = v0 + vl;
        if (gv < VV) {
            float2 af = __half22float2(a);
            float2 s = *reinterpret_cast<const float2*>(g_z0 + ((size_t)b * VV + gv) * 64 + 2 * lane);
            float inv = 1.0f / (float)max(deg_s[vl], 1);
            ob[2 * lane][vl]     = s.x + af.x * inv + bia.x;
            ob[2 * lane + 1][vl] = s.y + af.y * inv + bia.y;
        }
    }
    __syncthreads();

    for (int i = tid; i < 64 * 32; i += 256) {
        int o = i >> 5, v = i & 31;
        int gv = v0 + v;
        if (gv < VV)
            out[((size_t)b * OO + o) * VV + gv] = ob[o][v];
    }
}

extern "C" void kernel_launch(void* const* d_in, const int* in_sizes, int n_in,
                              void* d_out, int out_size) {
    const float* x    = (const float*)d_in[0];
    const int*   nbr  = (const int*)d_in[1];
    const int*   deg  = (const int*)d_in[2];
    const float* W    = (const float*)d_in[3];
    const float* bias = (const float*)d_in[4];
    float*       out  = (float*)d_out;

    cudaFuncSetAttribute(k1_gemm, cudaFuncAttributeMaxDynamicSharedMemorySize, SM_TOTAL);

    dim3 g1(GX, BB);
    k1_gemm<<<g1, 256, SM_TOTAL>>>(x, W);

    dim3 g2((VV + 31) / 32, BB);
    k2_gather<<<g2, 256>>>(nbr, deg, bias, out);
}